// round 16
// baseline (speedup 1.0000x reference)
#include <cuda_runtime.h>
#include <cstdint>
#include <math.h>

#define B 8
#define M 4096
#define E 1024
#define D 128
#define NCAT 64

#define SPLIT 4
#define M_PER (M / SPLIT)        // 1024
#define E_TILE 256
#define MCHUNK 128
#define NCHUNK (M_PER / MCHUNK)  // 8
#define NIB32_STRIDE 33

// ---------------- scratch (device globals; no allocations) ----------------
__device__ float d_part[(size_t)SPLIT * B * E * D];  // 16 MB partial agg
__device__ float d_agg[(size_t)B * E * D];           // 4 MB
__device__ float d_G[(size_t)B * E * D];             // 4 MB edge scores
__device__ float d_t[(size_t)B * E * D];             // 4 MB agg*attn
__device__ float d_WattT[D * D];
__device__ float d_v[D];
__device__ float d_cmax_p[B * 32 * D];
__device__ float d_csum_p[B * 32 * D];
__device__ float d_a[B * E];
__device__ float d_asum[B];
__device__ float d_spart[B * 32 * D];

// ---------------- helpers ----------------
__device__ __forceinline__ void cp16(void* dst, const void* src) {
    unsigned du = (unsigned)__cvta_generic_to_shared(dst);
    asm volatile("cp.async.cg.shared.global [%0], [%1], 16;" :: "r"(du), "l"(src));
}
__device__ __forceinline__ void cp_commit() {
    asm volatile("cp.async.commit_group;" ::: "memory");
}
__device__ __forceinline__ void cp_wait0() {
    asm volatile("cp.async.wait_group 0;" ::: "memory");
}
__device__ __forceinline__ void pref_l2(const void* p) {
    asm volatile("prefetch.global.L2 [%0];" :: "l"(p));
}

__device__ __forceinline__ unsigned nib8(float4 a, float4 b) {
    return (unsigned)(a.x != 0.0f)
         | ((unsigned)(a.y != 0.0f) << 1)
         | ((unsigned)(a.z != 0.0f) << 2)
         | ((unsigned)(a.w != 0.0f) << 3)
         | ((unsigned)(b.x != 0.0f) << 4)
         | ((unsigned)(b.y != 0.0f) << 5)
         | ((unsigned)(b.z != 0.0f) << 6)
         | ((unsigned)(b.w != 0.0f) << 7);
}

// ---------------- K0: parallel W_att transpose (16 tiles) + v in block 0 ----
__global__ __launch_bounds__(256) void k0_trans(const float* __restrict__ W_att,
                                                const float* __restrict__ W_proj,
                                                const float* __restrict__ ec_att_w) {
    __shared__ float tile[32][33];
    const int bx = blockIdx.x & 3;
    const int by = blockIdx.x >> 2;
    const int lx = threadIdx.x & 31;
    const int ly = threadIdx.x >> 5;

    const int x = bx * 32 + lx;
#pragma unroll
    for (int r = 0; r < 32; r += 8)
        tile[ly + r][lx] = W_att[(size_t)(by * 32 + ly + r) * D + x];
    __syncthreads();

    const int tx = bx * 32 + ly;
    const int ty = by * 32 + lx;
#pragma unroll
    for (int r = 0; r < 32; r += 8)
        d_WattT[(size_t)(tx + r) * D + ty] = tile[lx][ly + r];

    if (blockIdx.x == 0 && threadIdx.x < 128) {
        const int t = threadIdx.x;
        float acc = 0.0f;
#pragma unroll 16
        for (int i = 0; i < D; i++) acc += ec_att_w[i] * W_proj[i * D + t];
        d_v[t] = acc;
    }
}

// no-op spacer: k0, knop, k1, k2 -> 4th launch (profiled) = k2
__global__ void knop(void) {}

// ---------------- K1: agg partials = inc^T @ nf (R10-verified bit-scan) ----
__global__ __launch_bounds__(1024, 1) void k1_agg(const float* __restrict__ nf,
                                                  const float* __restrict__ inc) {
    extern __shared__ char smem_raw[];
    float* nf_s = (float*)smem_raw;                                   // 128KB
    unsigned* nib32_s = (unsigned*)(smem_raw + 2 * MCHUNK * D * 4);   // 8448B

    const int e0 = blockIdx.x * E_TILE;
    const int b  = blockIdx.y;
    const int sp = blockIdx.z;
    const int tid = threadIdx.x;
    const int w = tid >> 5;
    const int l = tid & 31;

    float4 acc[8];
#pragma unroll
    for (int j = 0; j < 8; j++) acc[j] = make_float4(0.f, 0.f, 0.f, 0.f);

    const float* nf_b  = nf  + (size_t)b * M * D;
    const float* inc_b = inc + (size_t)b * M * E;

    {
        const int mb = sp * M_PER;
        const float4* src = (const float4*)(nf_b + (size_t)mb * D);
        float4* dst = (float4*)nf_s;
#pragma unroll
        for (int i = 0; i < 4; i++) cp16(&dst[tid + i * 1024], &src[tid + i * 1024]);
        cp_commit();
        unsigned packed = 0;
#pragma unroll
        for (int r = 0; r < 4; r++) {
            const int row = 4 * w + r;
            const float* rp = inc_b + (size_t)(mb + row) * E + e0 + 8 * l;
            float4 a4 = *(const float4*)rp;
            float4 b4 = *(const float4*)(rp + 4);
            packed |= nib8(a4, b4) << (8 * r);
        }
        nib32_s[w * NIB32_STRIDE + l] = packed;
        cp_wait0();
    }
    __syncthreads();

    for (int c = 0; c < NCHUNK; c++) {
        const int p = c & 1;
        const int q = p ^ 1;
        const bool pre = (c + 1 < NCHUNK);
        const int mbn = sp * M_PER + (c + 1) * MCHUNK;

        if (pre) {
            const float4* src = (const float4*)(nf_b + (size_t)mbn * D);
            float4* dst = (float4*)(nf_s + (size_t)q * MCHUNK * D);
#pragma unroll
            for (int i = 0; i < 4; i++) cp16(&dst[tid + i * 1024], &src[tid + i * 1024]);
            cp_commit();
#pragma unroll
            for (int r = 0; r < 4; r++)
                pref_l2(inc_b + (size_t)(mbn + 4 * w + r) * E + e0 + 8 * l);
        }

        const unsigned* nibp = nib32_s + p * 32 * NIB32_STRIDE;
        const float* nfp = nf_s + (size_t)p * MCHUNK * D;
#pragma unroll
        for (int h = 0; h < 4; h++) {
            unsigned word = nibp[(h * 8 + (l >> 2)) * NIB32_STRIDE + w];
            unsigned byte_ = (word >> ((l & 3) * 8)) & 0xFFu;
            unsigned msk[8];
#pragma unroll
            for (int j = 0; j < 8; j++)
                msk[j] = __ballot_sync(0xffffffffu, (byte_ >> j) & 1u);
            const float4* nfrow = (const float4*)(nfp + (size_t)h * 32 * D);
#pragma unroll
            for (int j = 0; j < 8; j++) {
                unsigned ms = msk[j];
                while (ms) {
                    int r = __ffs(ms) - 1;
                    ms &= ms - 1;
                    float4 x = nfrow[r * (D / 4) + l];
                    acc[j].x += x.x; acc[j].y += x.y;
                    acc[j].z += x.z; acc[j].w += x.w;
                }
            }
        }

        if (pre) {
            unsigned packed = 0;
#pragma unroll
            for (int r = 0; r < 4; r++) {
                const int row = 4 * w + r;
                const float* rp = inc_b + (size_t)(mbn + row) * E + e0 + 8 * l;
                float4 a4 = *(const float4*)rp;
                float4 b4 = *(const float4*)(rp + 4);
                packed |= nib8(a4, b4) << (8 * r);
            }
            nib32_s[q * 32 * NIB32_STRIDE + w * NIB32_STRIDE + l] = packed;
        }
        cp_wait0();
        __syncthreads();
    }

    size_t base = (((size_t)sp * B + b) * E + (e0 + 8 * w)) * D + 4 * l;
#pragma unroll
    for (int j = 0; j < 8; j++)
        *(float4*)&d_part[base + (size_t)j * D] = acc[j];
}

// ---------------- K2: reduce partials -> agg, G = agg @ W_att^T, fused stats ----
// 256 blocks x 256 threads, 32 rows (= one chunk)/block; full W^T in smem;
// 96KB smem -> 2 blocks/SM (latency overlap across blocks).
__global__ __launch_bounds__(256) void k2_gemm(void) {
    extern __shared__ char sm2[];
    float* WT_s  = (float*)sm2;                       // [128][128] 64KB
    float* agg_s = (float*)(sm2 + 65536);             // [32][128] 16KB
    float* Gs    = (float*)(sm2 + 65536 + 16384);     // [32][128] 16KB

    const int r0 = blockIdx.x * 32;
    const int tid = threadIdx.x;

    // stage full W^T (4096 float4 / 256 thr = 16 each)
    {
        const float4* srcW = (const float4*)d_WattT;
        float4* dstW = (float4*)WT_s;
#pragma unroll
        for (int i = 0; i < 16; i++)
            dstW[tid + i * 256] = srcW[tid + i * 256];
    }
    // stage agg tile (fused 4-way split reduction), also write d_agg
    {
        const size_t stride = (size_t)B * E * D / 4;
#pragma unroll
        for (int i = 0; i < 4; i++) {
            int idx = tid + i * 256;             // 1024 float4 = 32 rows
            size_t base = (size_t)r0 * (D / 4) + idx;
            float4 s = make_float4(0.f, 0.f, 0.f, 0.f);
#pragma unroll
            for (int sp = 0; sp < SPLIT; sp++) {
                float4 v = ((const float4*)d_part)[sp * stride + base];
                s.x += v.x; s.y += v.y; s.z += v.z; s.w += v.w;
            }
            ((float4*)agg_s)[idx] = s;
            ((float4*)d_agg)[base] = s;
        }
    }
    __syncthreads();

    const int wrp = tid >> 5;        // 8 warps
    const int l = tid & 31;
    const int c0 = l * 4;
    const int rbase = wrp * 4;       // 8 warps x 4 rows = 32

    float4 acc0 = make_float4(0, 0, 0, 0), acc1 = acc0, acc2 = acc0, acc3 = acc0;
#pragma unroll 8
    for (int k = 0; k < D; k++) {
        float4 wv = *(const float4*)&WT_s[k * D + c0];
        float a0 = agg_s[(rbase + 0) * D + k];
        float a1 = agg_s[(rbase + 1) * D + k];
        float a2 = agg_s[(rbase + 2) * D + k];
        float a3 = agg_s[(rbase + 3) * D + k];
        acc0.x += a0 * wv.x; acc0.y += a0 * wv.y; acc0.z += a0 * wv.z; acc0.w += a0 * wv.w;
        acc1.x += a1 * wv.x; acc1.y += a1 * wv.y; acc1.z += a1 * wv.z; acc1.w += a1 * wv.w;
        acc2.x += a2 * wv.x; acc2.y += a2 * wv.y; acc2.z += a2 * wv.z; acc2.w += a2 * wv.w;
        acc3.x += a3 * wv.x; acc3.y += a3 * wv.y; acc3.z += a3 * wv.z; acc3.w += a3 * wv.w;
    }
    *(float4*)&Gs[(rbase + 0) * D + c0] = acc0;
    *(float4*)&Gs[(rbase + 1) * D + c0] = acc1;
    *(float4*)&Gs[(rbase + 2) * D + c0] = acc2;
    *(float4*)&Gs[(rbase + 3) * D + c0] = acc3;
    *(float4*)&d_G[(size_t)(r0 + rbase + 0) * D + c0] = acc0;
    *(float4*)&d_G[(size_t)(r0 + rbase + 1) * D + c0] = acc1;
    *(float4*)&d_G[(size_t)(r0 + rbase + 2) * D + c0] = acc2;
    *(float4*)&d_G[(size_t)(r0 + rbase + 3) * D + c0] = acc3;
    __syncthreads();

    // fused per-chunk softmax stats: this block's 32 rows == one edge chunk
    if (tid < 128) {
        const int d = tid;
        float mx = -INFINITY;
#pragma unroll
        for (int e = 0; e < 32; e++) mx = fmaxf(mx, Gs[e * D + d]);
        float sum = 0.0f;
#pragma unroll
        for (int e = 0; e < 32; e++) sum += __expf(Gs[e * D + d] - mx);
        const int bb = blockIdx.x >> 5;   // 32 chunks per batch
        const int ch = blockIdx.x & 31;
        d_cmax_p[(bb * 32 + ch) * D + d] = mx;
        d_csum_p[(bb * 32 + ch) * D + d] = sum;
    }
}

// ---------------- K4: fused stat-combine + batched warp-per-edge attn -------
__global__ __launch_bounds__(256) void k4(void) {
    __shared__ float cm_s[D], cs_s[D];
    const int b = blockIdx.y;
    const int e_base = blockIdx.x * 32;
    const int tid = threadIdx.x;

    if (tid < 128) {
        const int d = tid;
        const float* mp = d_cmax_p + (size_t)b * 32 * D + d;
        const float* sp = d_csum_p + (size_t)b * 32 * D + d;
        float m[32], s[32];
#pragma unroll
        for (int ch = 0; ch < 32; ch++) { m[ch] = mp[(size_t)ch * D]; s[ch] = sp[(size_t)ch * D]; }
        float mx = m[0];
#pragma unroll
        for (int ch = 1; ch < 32; ch++) mx = fmaxf(mx, m[ch]);
        float sum = 0.0f;
#pragma unroll
        for (int ch = 0; ch < 32; ch++) sum += s[ch] * __expf(m[ch] - mx);
        cm_s[d] = mx;
        cs_s[d] = sum;
    }
    __syncthreads();

    const int l = tid & 31;
    const int wrp = tid >> 5;
    const size_t r0 = (size_t)b * E + e_base + wrp * 4;

    float4 g[4], ag[4];
#pragma unroll
    for (int it = 0; it < 4; it++) {
        g[it]  = *(const float4*)&d_G[(r0 + it) * D + l * 4];
        ag[it] = *(const float4*)&d_agg[(r0 + it) * D + l * 4];
    }

    float4 v4 = *(const float4*)&d_v[l * 4];
    float4 cm = *(const float4*)&cm_s[l * 4];
    float4 cs = *(const float4*)&cs_s[l * 4];
#pragma unroll
    for (int it = 0; it < 4; it++) {
        float4 t;
        t.x = ag[it].x * (__expf(g[it].x - cm.x) / cs.x);
        t.y = ag[it].y * (__expf(g[it].y - cm.y) / cs.y);
        t.z = ag[it].z * (__expf(g[it].z - cm.z) / cs.z);
        t.w = ag[it].w * (__expf(g[it].w - cm.w) / cs.w);
        *(float4*)&d_t[(r0 + it) * D + l * 4] = t;
        float p = t.x * v4.x + t.y * v4.y + t.z * v4.z + t.w * v4.w;
#pragma unroll
        for (int o = 16; o; o >>= 1) p += __shfl_xor_sync(0xffffffffu, p, o);
        if (l == 0) d_a[r0 + it] = p;
    }
}

// ---------------- K5a: fused a-softmax stats + pooling (2 chunks/block) ------
__global__ __launch_bounds__(128) void k5a(void) {
    __shared__ float red[128];
    __shared__ float ws[2][32];
    const int b = blockIdx.y;
    const int ch0 = blockIdx.x * 2;
    const int d = threadIdx.x;

    float av[8];
#pragma unroll
    for (int i = 0; i < 8; i++) av[i] = d_a[b * E + d + i * 128];
    float mx = av[0];
#pragma unroll
    for (int i = 1; i < 8; i++) mx = fmaxf(mx, av[i]);
    red[d] = mx; __syncthreads();
    for (int s = 64; s; s >>= 1) { if (d < s) red[d] = fmaxf(red[d], red[d + s]); __syncthreads(); }
    float gmx = red[0]; __syncthreads();
    float sum = 0.0f;
#pragma unroll
    for (int i = 0; i < 8; i++) sum += __expf(av[i] - gmx);
    red[d] = sum; __syncthreads();
    for (int s = 64; s; s >>= 1) { if (d < s) red[d] += red[d + s]; __syncthreads(); }
    if (blockIdx.x == 0 && d == 0) d_asum[b] = red[0];

    if (d < 64) ws[d >> 5][d & 31] = __expf(d_a[b * E + (ch0 + (d >> 5)) * 32 + (d & 31)] - gmx);
    __syncthreads();

#pragma unroll
    for (int c = 0; c < 2; c++) {
        const float* tp = d_t + ((size_t)b * E + (ch0 + c) * 32) * D + d;
        float acc = 0.0f;
#pragma unroll
        for (int e = 0; e < 32; e++) acc += ws[c][e] * tp[(size_t)e * D];
        d_spart[(b * 32 + ch0 + c) * D + d] = acc;
    }
}

// ---------------- K6: final projections -> logits ----------------
__global__ __launch_bounds__(128) void k6(const float* __restrict__ W_proj,
                                          const float* __restrict__ ec_proj_w,
                                          const float* __restrict__ ec_proj_b,
                                          const float* __restrict__ fc_w,
                                          const float* __restrict__ fc_b,
                                          float* __restrict__ out) {
    __shared__ float sf[D], ef[D], ov[D];
    const int b = blockIdx.x, t = threadIdx.x;
    float s = 0.0f;
#pragma unroll
    for (int ch = 0; ch < 32; ch++) s += d_spart[(b * 32 + ch) * D + t];
    sf[t] = s / d_asum[b];
    __syncthreads();
    float a1 = 0.0f;
#pragma unroll 16
    for (int j = 0; j < D; j++) a1 += sf[j] * W_proj[t * D + j];
    ef[t] = a1;
    __syncthreads();
    float a2 = 0.0f;
#pragma unroll 16
    for (int j = 0; j < D; j++) a2 += ef[j] * ec_proj_w[t * D + j];
    ov[t] = a2 + ec_proj_b[t];
    __syncthreads();
    if (t < NCAT) {
        float a3 = 0.0f;
#pragma unroll 16
        for (int j = 0; j < D; j++) a3 += ov[j] * fc_w[t * D + j];
        out[b * NCAT + t] = a3 + fc_b[t];
    }
}

// ---------------- launch ----------------
extern "C" void kernel_launch(void* const* d_in, const int* in_sizes, int n_in,
                              void* d_out, int out_size) {
    const float* nf        = (const float*)d_in[0];
    const float* inc       = (const float*)d_in[1];
    const float* W_att     = (const float*)d_in[2];
    const float* W_proj    = (const float*)d_in[3];
    const float* ec_att_w  = (const float*)d_in[4];
    const float* ec_proj_w = (const float*)d_in[5];
    const float* ec_proj_b = (const float*)d_in[6];
    const float* fc_w      = (const float*)d_in[7];
    const float* fc_b      = (const float*)d_in[8];
    float* out = (float*)d_out;

    const int K1_SMEM = 2 * MCHUNK * D * 4 + 2 * 32 * NIB32_STRIDE * 4;  // 139520
    const int K2_SMEM = 65536 + 16384 + 16384;                           // 98304
    cudaFuncSetAttribute(k1_agg, cudaFuncAttributeMaxDynamicSharedMemorySize, K1_SMEM);
    cudaFuncSetAttribute(k2_gemm, cudaFuncAttributeMaxDynamicSharedMemorySize, K2_SMEM);

    k0_trans<<<16, 256>>>(W_att, W_proj, ec_att_w);
    knop<<<1, 32>>>();
    k1_agg<<<dim3(E / E_TILE, B, SPLIT), 1024, K1_SMEM>>>(nf, inc);
    k2_gemm<<<(B * E) / 32, 256, K2_SMEM>>>();    // 4th launch -> profiled
    k4<<<dim3(32, B), 256>>>();
    k5a<<<dim3(16, B), 128>>>();
    k6<<<B, 128>>>(W_proj, ec_proj_w, ec_proj_b, fc_w, fc_b, out);
}

// round 17
// speedup vs baseline: 1.0373x; 1.0373x over previous
#include <cuda_runtime.h>
#include <cstdint>
#include <math.h>

#define B 8
#define M 4096
#define E 1024
#define D 128
#define NCAT 64

#define SPLIT 4
#define M_PER (M / SPLIT)        // 1024
#define E_TILE 256
#define MCHUNK 128
#define NCHUNK (M_PER / MCHUNK)  // 8
#define NIB32_STRIDE 33

// ---------------- scratch (device globals; no allocations) ----------------
__device__ float d_part[(size_t)SPLIT * B * E * D];  // 16 MB partial agg
__device__ float d_agg[(size_t)B * E * D];           // 4 MB
__device__ float d_G[(size_t)B * E * D];             // 4 MB edge scores
__device__ float d_t[(size_t)B * E * D];             // 4 MB agg*attn
__device__ float d_WattT[D * D];
__device__ float d_v[D];
__device__ float d_cmax_p[B * 32 * D];
__device__ float d_csum_p[B * 32 * D];
__device__ float d_a[B * E];
__device__ float d_asum[B];
__device__ float d_spart[B * 32 * D];

// ---------------- helpers ----------------
__device__ __forceinline__ void cp16(void* dst, const void* src) {
    unsigned du = (unsigned)__cvta_generic_to_shared(dst);
    asm volatile("cp.async.cg.shared.global [%0], [%1], 16;" :: "r"(du), "l"(src));
}
__device__ __forceinline__ void cp_commit() {
    asm volatile("cp.async.commit_group;" ::: "memory");
}
__device__ __forceinline__ void cp_wait0() {
    asm volatile("cp.async.wait_group 0;" ::: "memory");
}
__device__ __forceinline__ void pref_l2(const void* p) {
    asm volatile("prefetch.global.L2 [%0];" :: "l"(p));
}

__device__ __forceinline__ unsigned nib8(float4 a, float4 b) {
    return (unsigned)(a.x != 0.0f)
         | ((unsigned)(a.y != 0.0f) << 1)
         | ((unsigned)(a.z != 0.0f) << 2)
         | ((unsigned)(a.w != 0.0f) << 3)
         | ((unsigned)(b.x != 0.0f) << 4)
         | ((unsigned)(b.y != 0.0f) << 5)
         | ((unsigned)(b.z != 0.0f) << 6)
         | ((unsigned)(b.w != 0.0f) << 7);
}

// ---------------- K0: parallel W_att transpose (16 tiles) + v in block 0 ----
__global__ __launch_bounds__(256) void k0_trans(const float* __restrict__ W_att,
                                                const float* __restrict__ W_proj,
                                                const float* __restrict__ ec_att_w) {
    __shared__ float tile[32][33];
    const int bx = blockIdx.x & 3;
    const int by = blockIdx.x >> 2;
    const int lx = threadIdx.x & 31;
    const int ly = threadIdx.x >> 5;

    const int x = bx * 32 + lx;
#pragma unroll
    for (int r = 0; r < 32; r += 8)
        tile[ly + r][lx] = W_att[(size_t)(by * 32 + ly + r) * D + x];
    __syncthreads();

    const int tx = bx * 32 + ly;
    const int ty = by * 32 + lx;
#pragma unroll
    for (int r = 0; r < 32; r += 8)
        d_WattT[(size_t)(tx + r) * D + ty] = tile[lx][ly + r];

    if (blockIdx.x == 0 && threadIdx.x < 128) {
        const int t = threadIdx.x;
        float acc = 0.0f;
#pragma unroll 16
        for (int i = 0; i < D; i++) acc += ec_att_w[i] * W_proj[i * D + t];
        d_v[t] = acc;
    }
}

// ---------------- K1: agg partials = inc^T @ nf (R10-verified bit-scan) ----
__global__ __launch_bounds__(1024, 1) void k1_agg(const float* __restrict__ nf,
                                                  const float* __restrict__ inc) {
    extern __shared__ char smem_raw[];
    float* nf_s = (float*)smem_raw;                                   // 128KB
    unsigned* nib32_s = (unsigned*)(smem_raw + 2 * MCHUNK * D * 4);   // 8448B

    const int e0 = blockIdx.x * E_TILE;
    const int b  = blockIdx.y;
    const int sp = blockIdx.z;
    const int tid = threadIdx.x;
    const int w = tid >> 5;
    const int l = tid & 31;

    float4 acc[8];
#pragma unroll
    for (int j = 0; j < 8; j++) acc[j] = make_float4(0.f, 0.f, 0.f, 0.f);

    const float* nf_b  = nf  + (size_t)b * M * D;
    const float* inc_b = inc + (size_t)b * M * E;

    {
        const int mb = sp * M_PER;
        const float4* src = (const float4*)(nf_b + (size_t)mb * D);
        float4* dst = (float4*)nf_s;
#pragma unroll
        for (int i = 0; i < 4; i++) cp16(&dst[tid + i * 1024], &src[tid + i * 1024]);
        cp_commit();
        unsigned packed = 0;
#pragma unroll
        for (int r = 0; r < 4; r++) {
            const int row = 4 * w + r;
            const float* rp = inc_b + (size_t)(mb + row) * E + e0 + 8 * l;
            float4 a4 = *(const float4*)rp;
            float4 b4 = *(const float4*)(rp + 4);
            packed |= nib8(a4, b4) << (8 * r);
        }
        nib32_s[w * NIB32_STRIDE + l] = packed;
        cp_wait0();
    }
    __syncthreads();

    for (int c = 0; c < NCHUNK; c++) {
        const int p = c & 1;
        const int q = p ^ 1;
        const bool pre = (c + 1 < NCHUNK);
        const int mbn = sp * M_PER + (c + 1) * MCHUNK;

        if (pre) {
            const float4* src = (const float4*)(nf_b + (size_t)mbn * D);
            float4* dst = (float4*)(nf_s + (size_t)q * MCHUNK * D);
#pragma unroll
            for (int i = 0; i < 4; i++) cp16(&dst[tid + i * 1024], &src[tid + i * 1024]);
            cp_commit();
#pragma unroll
            for (int r = 0; r < 4; r++)
                pref_l2(inc_b + (size_t)(mbn + 4 * w + r) * E + e0 + 8 * l);
        }

        const unsigned* nibp = nib32_s + p * 32 * NIB32_STRIDE;
        const float* nfp = nf_s + (size_t)p * MCHUNK * D;
#pragma unroll
        for (int h = 0; h < 4; h++) {
            unsigned word = nibp[(h * 8 + (l >> 2)) * NIB32_STRIDE + w];
            unsigned byte_ = (word >> ((l & 3) * 8)) & 0xFFu;
            unsigned msk[8];
#pragma unroll
            for (int j = 0; j < 8; j++)
                msk[j] = __ballot_sync(0xffffffffu, (byte_ >> j) & 1u);
            const float4* nfrow = (const float4*)(nfp + (size_t)h * 32 * D);
#pragma unroll
            for (int j = 0; j < 8; j++) {
                unsigned ms = msk[j];
                while (ms) {
                    int r = __ffs(ms) - 1;
                    ms &= ms - 1;
                    float4 x = nfrow[r * (D / 4) + l];
                    acc[j].x += x.x; acc[j].y += x.y;
                    acc[j].z += x.z; acc[j].w += x.w;
                }
            }
        }

        if (pre) {
            unsigned packed = 0;
#pragma unroll
            for (int r = 0; r < 4; r++) {
                const int row = 4 * w + r;
                const float* rp = inc_b + (size_t)(mbn + row) * E + e0 + 8 * l;
                float4 a4 = *(const float4*)rp;
                float4 b4 = *(const float4*)(rp + 4);
                packed |= nib8(a4, b4) << (8 * r);
            }
            nib32_s[q * 32 * NIB32_STRIDE + w * NIB32_STRIDE + l] = packed;
        }
        cp_wait0();
        __syncthreads();
    }

    size_t base = (((size_t)sp * B + b) * E + (e0 + 8 * w)) * D + 4 * l;
#pragma unroll
    for (int j = 0; j < 8; j++)
        *(float4*)&d_part[base + (size_t)j * D] = acc[j];
}

// ---------------- K2: reduce partials -> agg, G = agg @ W_att^T, fused stats ----
// R15-verified: 128 blocks x 512 threads; full W^T in smem; 64 rows/block.
__global__ __launch_bounds__(512) void k2_gemm(void) {
    extern __shared__ char sm2[];
    float* WT_s  = (float*)sm2;                       // 64KB
    float* agg_s = (float*)(sm2 + 65536);             // 32KB
    float* Gs    = (float*)(sm2 + 65536 + 32768);     // 32KB

    const int r0 = blockIdx.x * 64;
    const int tid = threadIdx.x;

    {
        const float4* srcW = (const float4*)d_WattT;
        float4* dstW = (float4*)WT_s;
#pragma unroll
        for (int i = 0; i < 8; i++)
            dstW[tid + i * 512] = srcW[tid + i * 512];
    }
    {
        const size_t stride = (size_t)B * E * D / 4;
#pragma unroll
        for (int i = 0; i < 4; i++) {
            int idx = tid + i * 512;
            size_t base = (size_t)r0 * (D / 4) + idx;
            float4 s = make_float4(0.f, 0.f, 0.f, 0.f);
#pragma unroll
            for (int sp = 0; sp < SPLIT; sp++) {
                float4 v = ((const float4*)d_part)[sp * stride + base];
                s.x += v.x; s.y += v.y; s.z += v.z; s.w += v.w;
            }
            ((float4*)agg_s)[idx] = s;
            ((float4*)d_agg)[base] = s;
        }
    }
    __syncthreads();

    const int wrp = tid >> 5;
    const int l = tid & 31;
    const int c0 = l * 4;
    const int rbase = wrp * 4;

    float4 acc0 = make_float4(0, 0, 0, 0), acc1 = acc0, acc2 = acc0, acc3 = acc0;
#pragma unroll 8
    for (int k = 0; k < D; k++) {
        float4 wv = *(const float4*)&WT_s[k * D + c0];
        float a0 = agg_s[(rbase + 0) * D + k];
        float a1 = agg_s[(rbase + 1) * D + k];
        float a2 = agg_s[(rbase + 2) * D + k];
        float a3 = agg_s[(rbase + 3) * D + k];
        acc0.x += a0 * wv.x; acc0.y += a0 * wv.y; acc0.z += a0 * wv.z; acc0.w += a0 * wv.w;
        acc1.x += a1 * wv.x; acc1.y += a1 * wv.y; acc1.z += a1 * wv.z; acc1.w += a1 * wv.w;
        acc2.x += a2 * wv.x; acc2.y += a2 * wv.y; acc2.z += a2 * wv.z; acc2.w += a2 * wv.w;
        acc3.x += a3 * wv.x; acc3.y += a3 * wv.y; acc3.z += a3 * wv.z; acc3.w += a3 * wv.w;
    }
    *(float4*)&Gs[(rbase + 0) * D + c0] = acc0;
    *(float4*)&Gs[(rbase + 1) * D + c0] = acc1;
    *(float4*)&Gs[(rbase + 2) * D + c0] = acc2;
    *(float4*)&Gs[(rbase + 3) * D + c0] = acc3;
    *(float4*)&d_G[(size_t)(r0 + rbase + 0) * D + c0] = acc0;
    *(float4*)&d_G[(size_t)(r0 + rbase + 1) * D + c0] = acc1;
    *(float4*)&d_G[(size_t)(r0 + rbase + 2) * D + c0] = acc2;
    *(float4*)&d_G[(size_t)(r0 + rbase + 3) * D + c0] = acc3;
    __syncthreads();

    if (tid < 256) {
        const int half = tid >> 7;
        const int d = tid & 127;
        const float* g = Gs + (size_t)half * 32 * D;
        float mx = -INFINITY;
#pragma unroll
        for (int e = 0; e < 32; e++) mx = fmaxf(mx, g[e * D + d]);
        float sum = 0.0f;
#pragma unroll
        for (int e = 0; e < 32; e++) sum += __expf(g[e * D + d] - mx);
        const int bb = blockIdx.x >> 4;
        const int ch = ((blockIdx.x & 15) << 1) + half;
        d_cmax_p[(bb * 32 + ch) * D + d] = mx;
        d_csum_p[(bb * 32 + ch) * D + d] = sum;
    }
}

// ---------------- K4: fused stat-combine + batched warp-per-edge attn -------
__global__ __launch_bounds__(256) void k4(void) {
    __shared__ float cm_s[D], cs_s[D];
    const int b = blockIdx.y;
    const int e_base = blockIdx.x * 32;
    const int tid = threadIdx.x;

    if (tid < 128) {
        const int d = tid;
        const float* mp = d_cmax_p + (size_t)b * 32 * D + d;
        const float* sp = d_csum_p + (size_t)b * 32 * D + d;
        float m[32], s[32];
#pragma unroll
        for (int ch = 0; ch < 32; ch++) { m[ch] = mp[(size_t)ch * D]; s[ch] = sp[(size_t)ch * D]; }
        float mx = m[0];
#pragma unroll
        for (int ch = 1; ch < 32; ch++) mx = fmaxf(mx, m[ch]);
        float sum = 0.0f;
#pragma unroll
        for (int ch = 0; ch < 32; ch++) sum += s[ch] * __expf(m[ch] - mx);
        cm_s[d] = mx;
        cs_s[d] = sum;
    }
    __syncthreads();

    const int l = tid & 31;
    const int wrp = tid >> 5;
    const size_t r0 = (size_t)b * E + e_base + wrp * 4;

    float4 g[4], ag[4];
#pragma unroll
    for (int it = 0; it < 4; it++) {
        g[it]  = *(const float4*)&d_G[(r0 + it) * D + l * 4];
        ag[it] = *(const float4*)&d_agg[(r0 + it) * D + l * 4];
    }

    float4 v4 = *(const float4*)&d_v[l * 4];
    float4 cm = *(const float4*)&cm_s[l * 4];
    float4 cs = *(const float4*)&cs_s[l * 4];
#pragma unroll
    for (int it = 0; it < 4; it++) {
        float4 t;
        t.x = ag[it].x * (__expf(g[it].x - cm.x) / cs.x);
        t.y = ag[it].y * (__expf(g[it].y - cm.y) / cs.y);
        t.z = ag[it].z * (__expf(g[it].z - cm.z) / cs.z);
        t.w = ag[it].w * (__expf(g[it].w - cm.w) / cs.w);
        *(float4*)&d_t[(r0 + it) * D + l * 4] = t;
        float p = t.x * v4.x + t.y * v4.y + t.z * v4.z + t.w * v4.w;
#pragma unroll
        for (int o = 16; o; o >>= 1) p += __shfl_xor_sync(0xffffffffu, p, o);
        if (l == 0) d_a[r0 + it] = p;
    }
}

// ---------------- K5a: fused a-softmax stats + pooling, 1 chunk/block -------
// grid (32, B) = 256 blocks x 128 thr; pooling loads batched into registers.
__global__ __launch_bounds__(128) void k5a(void) {
    __shared__ float red[128];
    __shared__ float ws[32];
    const int b = blockIdx.y;
    const int ch = blockIdx.x;
    const int d = threadIdx.x;

    // redundant per-block a-softmax stats (4KB per batch, L2-resident)
    float av[8];
#pragma unroll
    for (int i = 0; i < 8; i++) av[i] = d_a[b * E + d + i * 128];
    float mx = av[0];
#pragma unroll
    for (int i = 1; i < 8; i++) mx = fmaxf(mx, av[i]);
    red[d] = mx; __syncthreads();
    for (int s = 64; s; s >>= 1) { if (d < s) red[d] = fmaxf(red[d], red[d + s]); __syncthreads(); }
    float gmx = red[0]; __syncthreads();
    float sum = 0.0f;
#pragma unroll
    for (int i = 0; i < 8; i++) sum += __expf(av[i] - gmx);
    red[d] = sum; __syncthreads();
    for (int s = 64; s; s >>= 1) { if (d < s) red[d] += red[d + s]; __syncthreads(); }
    if (blockIdx.x == 0 && d == 0) d_asum[b] = red[0];

    if (d < 32) ws[d] = __expf(d_a[b * E + ch * 32 + d] - gmx);
    __syncthreads();

    // batched pooling loads (MLP 32), then accumulate
    const float* tp = d_t + ((size_t)b * E + ch * 32) * D + d;
    float tv[32];
#pragma unroll
    for (int e = 0; e < 32; e++) tv[e] = tp[(size_t)e * D];
    float acc = 0.0f;
#pragma unroll
    for (int e = 0; e < 32; e++) acc += ws[e] * tv[e];
    d_spart[(b * 32 + ch) * D + d] = acc;
}

// ---------------- K6: final projections -> logits ----------------
__global__ __launch_bounds__(128) void k6(const float* __restrict__ W_proj,
                                          const float* __restrict__ ec_proj_w,
                                          const float* __restrict__ ec_proj_b,
                                          const float* __restrict__ fc_w,
                                          const float* __restrict__ fc_b,
                                          float* __restrict__ out) {
    __shared__ float sf[D], ef[D], ov[D];
    const int b = blockIdx.x, t = threadIdx.x;
    float s = 0.0f;
#pragma unroll
    for (int ch = 0; ch < 32; ch++) s += d_spart[(b * 32 + ch) * D + t];
    sf[t] = s / d_asum[b];
    __syncthreads();
    float a1 = 0.0f;
#pragma unroll 16
    for (int j = 0; j < D; j++) a1 += sf[j] * W_proj[t * D + j];
    ef[t] = a1;
    __syncthreads();
    float a2 = 0.0f;
#pragma unroll 16
    for (int j = 0; j < D; j++) a2 += ef[j] * ec_proj_w[t * D + j];
    ov[t] = a2 + ec_proj_b[t];
    __syncthreads();
    if (t < NCAT) {
        float a3 = 0.0f;
#pragma unroll 16
        for (int j = 0; j < D; j++) a3 += ov[j] * fc_w[t * D + j];
        out[b * NCAT + t] = a3 + fc_b[t];
    }
}

// ---------------- launch ----------------
extern "C" void kernel_launch(void* const* d_in, const int* in_sizes, int n_in,
                              void* d_out, int out_size) {
    const float* nf        = (const float*)d_in[0];
    const float* inc       = (const float*)d_in[1];
    const float* W_att     = (const float*)d_in[2];
    const float* W_proj    = (const float*)d_in[3];
    const float* ec_att_w  = (const float*)d_in[4];
    const float* ec_proj_w = (const float*)d_in[5];
    const float* ec_proj_b = (const float*)d_in[6];
    const float* fc_w      = (const float*)d_in[7];
    const float* fc_b      = (const float*)d_in[8];
    float* out = (float*)d_out;

    const int K1_SMEM = 2 * MCHUNK * D * 4 + 2 * 32 * NIB32_STRIDE * 4;  // 139520
    const int K2_SMEM = 65536 + 32768 + 32768;                           // 131072
    cudaFuncSetAttribute(k1_agg, cudaFuncAttributeMaxDynamicSharedMemorySize, K1_SMEM);
    cudaFuncSetAttribute(k2_gemm, cudaFuncAttributeMaxDynamicSharedMemorySize, K2_SMEM);

    k0_trans<<<16, 256>>>(W_att, W_proj, ec_att_w);
    k1_agg<<<dim3(E / E_TILE, B, SPLIT), 1024, K1_SMEM>>>(nf, inc);
    k2_gemm<<<(B * E) / 64, 512, K2_SMEM>>>();
    k4<<<dim3(32, B), 256>>>();              // 4th launch -> profiled
    k5a<<<dim3(32, B), 128>>>();
    k6<<<B, 128>>>(W_proj, ec_proj_w, ec_proj_b, fc_w, fc_b, out);
}